// round 6
// baseline (speedup 1.0000x reference)
#include <cuda_runtime.h>
#include <cuda_bf16.h>

// Problem constants
#define BATCH 32
#define CH    256
#define HH    64
#define WW    64
#define HW    (HH*WW)            // 4096
#define HW4   (HW/4)             // 1024 float4 per plane
#define EPSV  1e-5f

#define CLUS    8                // CTAs per image (cluster size)
#define CPC     (CH/CLUS)        // 32 channels per CTA
#define THREADS 512              // threads per CTA; 2 float4-pixels each

// Global scratch: per-(image,CTA) partial pooled [max, sum] maps. 8 MB, L2-hot.
__device__ float g_part[BATCH * CLUS][2][HW];

// Dynamic SMEM layout (floats):
//   [0,      4096)  pooledMax
//   [4096,   8192)  pooledAvg
//   [8192,  12288)  att
//   [12288, 12582)  ws[3][2][49]
//   [12582, 12585)  bias[3]
#define SMEM_FLOATS (3 * HW + 3 * 2 * 49 + 3 + 5 /*pad*/)
#define SMEM_BYTES  (SMEM_FLOATS * 4)

#define CLUSTER_SYNC() do { \
    asm volatile("barrier.cluster.arrive.aligned;" ::: "memory"); \
    asm volatile("barrier.cluster.wait.aligned;" ::: "memory"); \
} while (0)

__device__ __forceinline__ float4 f4max(float4 a, float4 b) {
    return make_float4(fmaxf(a.x,b.x), fmaxf(a.y,b.y), fmaxf(a.z,b.z), fmaxf(a.w,b.w));
}
__device__ __forceinline__ float4 f4add(float4 a, float4 b) {
    return make_float4(a.x+b.x, a.y+b.y, a.z+b.z, a.w+b.w);
}

__global__ __cluster_dims__(CLUS, 1, 1) __launch_bounds__(THREADS, 1)
void fused_kernel(const float* __restrict__ x, float* __restrict__ out,
                  const float* __restrict__ w1,
                  const float* __restrict__ g1, const float* __restrict__ b1,
                  const float* __restrict__ m1, const float* __restrict__ v1,
                  const float* __restrict__ w2,
                  const float* __restrict__ g2, const float* __restrict__ b2,
                  const float* __restrict__ m2, const float* __restrict__ v2,
                  const float* __restrict__ w3,
                  const float* __restrict__ g3, const float* __restrict__ b3,
                  const float* __restrict__ m3, const float* __restrict__ v3) {
    extern __shared__ float smem[];
    float* pooledMax = smem;
    float* pooledAvg = smem + HW;
    float* att       = smem + 2 * HW;
    float* ws        = smem + 3 * HW;          // [3][2][49]
    float* bias      = ws + 3 * 2 * 49;

    const int t    = threadIdx.x;
    const int rank = blockIdx.x & (CLUS - 1);  // cluster rank (contiguous bids)
    const int b    = blockIdx.x >> 3;          // image index

    const int p0 = t;                           // float4 pixel indices
    const int p1 = t + THREADS;

    // ---------------- Phase 1: partial pool over my 32 channels ----------------
    const float4* xb = (const float4*)x + ((size_t)b * CH + (size_t)rank * CPC) * HW4;

    float4 a0 = xb[p0], a1 = xb[p1];
    float4 mxA = a0, smA = a0, mxB = a1, smB = a1;
#pragma unroll
    for (int ch = 1; ch < CPC; ch++) {
        float4 u = xb[(size_t)ch * HW4 + p0];
        float4 v = xb[(size_t)ch * HW4 + p1];
        mxA = f4max(mxA, u); smA = f4add(smA, u);
        mxB = f4max(mxB, v); smB = f4add(smB, v);
    }
    {
        float4* pm = (float4*)g_part[b * CLUS + rank][0];
        float4* ps = (float4*)g_part[b * CLUS + rank][1];
        pm[p0] = mxA; pm[p1] = mxB;
        ps[p0] = smA; ps[p1] = smB;
    }
    __threadfence();
    CLUSTER_SYNC();

    // ---------------- Phase 2: reduce 8 partials -> full pooled in SMEM --------
    {
        const float inv = 1.0f / (float)CH;
#pragma unroll
        for (int pp = 0; pp < 2; pp++) {
            int p = t + pp * THREADS;
            const float4* pm0 = (const float4*)g_part[b * CLUS][0];
            const float4* ps0 = (const float4*)g_part[b * CLUS][1];
            float4 mx = pm0[p];
            float4 sm = ps0[p];
#pragma unroll
            for (int r = 1; r < CLUS; r++) {
                const float4* pmr = (const float4*)g_part[b * CLUS + r][0];
                const float4* psr = (const float4*)g_part[b * CLUS + r][1];
                mx = f4max(mx, pmr[p]);
                sm = f4add(sm, psr[p]);
            }
            ((float4*)pooledMax)[p] = mx;
            ((float4*)pooledAvg)[p] = make_float4(sm.x*inv, sm.y*inv, sm.z*inv, sm.w*inv);
        }
    }

    // ---------------- Effective conv weights (BN folded) -----------------------
    if (t < 3) {
        const float* gg = (t == 0) ? g1 : (t == 1) ? g2 : g3;
        const float* be = (t == 0) ? b1 : (t == 1) ? b2 : b3;
        const float* mm = (t == 0) ? m1 : (t == 1) ? m2 : m3;
        const float* vv = (t == 0) ? v1 : (t == 1) ? v2 : v3;
        float s = gg[0] * rsqrtf(vv[0] + EPSV);
        bias[t] = be[0] - mm[0] * s;
    }
    for (int k = t; k < 3 * 2 * 49; k += THREADS) {
        int br = k / 98;
        int r  = k % 98;
        int i  = r / 49;
        int kk = r % 49;
        int kh = kk / 7, kw = kk % 7;
        float s, raw;
        if (br == 0)      { s = g1[0]*rsqrtf(v1[0]+EPSV); raw = w1[i*49 + kh*7 + kw]; }
        else if (br == 1) { s = g2[0]*rsqrtf(v2[0]+EPSV); raw = w2[i*49 + kw*7 + kh]; } // transposed
        else              { s = g3[0]*rsqrtf(v3[0]+EPSV); raw = w3[i*49 + kh*7 + kw]; }
        ws[k] = raw * s;
    }
    __syncthreads();

    // ---------------- Phase 3: full att map in SMEM (redundant per CTA) --------
#pragma unroll
    for (int i = 0; i < 8; i++) {
        int px = t + i * THREADS;
        int h = px >> 6, w = px & 63;
        float acc0 = 0.f, acc1 = 0.f, acc2 = 0.f;
#pragma unroll
        for (int kh = 0; kh < 7; kh++) {
            int hh = h + kh - 3;
            if (hh < 0 || hh >= HH) continue;
#pragma unroll
            for (int kw = 0; kw < 7; kw++) {
                int wv = w + kw - 3;
                if (wv < 0 || wv >= WW) continue;
                int off = hh * WW + wv;
                float pm = pooledMax[off];
                float pa = pooledAvg[off];
                int kk = kh * 7 + kw;
                acc0 = fmaf(ws[0*98 + 0*49 + kk], pm, acc0);
                acc0 = fmaf(ws[0*98 + 1*49 + kk], pa, acc0);
                acc1 = fmaf(ws[1*98 + 0*49 + kk], pm, acc1);
                acc1 = fmaf(ws[1*98 + 1*49 + kk], pa, acc1);
                acc2 = fmaf(ws[2*98 + 0*49 + kk], pm, acc2);
                acc2 = fmaf(ws[2*98 + 1*49 + kk], pa, acc2);
            }
        }
        float e0 = 1.0f / (1.0f + __expf(-(acc0 + bias[0])));
        float e1 = 1.0f / (1.0f + __expf(-(acc1 + bias[1])));
        float e2 = 1.0f / (1.0f + __expf(-(acc2 + bias[2])));
        att[px] = (e0 + e1 + e2) * (1.0f / 3.0f);
    }
    __syncthreads();

    // ---------------- Phase 4: out = x * att for my 32 channels ----------------
    // x was streamed by THIS CTA in phase 1 -> L2-hit re-read.
    {
        float4* ob = (float4*)out + ((size_t)b * CH + (size_t)rank * CPC) * HW4;
        const float4 at0 = ((const float4*)att)[p0];
        const float4 at1 = ((const float4*)att)[p1];
#pragma unroll 4
        for (int ch = 0; ch < CPC; ch++) {
            float4 xv = xb[(size_t)ch * HW4 + p0];
            float4 o;
            o.x = xv.x * at0.x; o.y = xv.y * at0.y;
            o.z = xv.z * at0.z; o.w = xv.w * at0.w;
            __stcs(ob + (size_t)ch * HW4 + p0, o);
            float4 yv = xb[(size_t)ch * HW4 + p1];
            float4 q;
            q.x = yv.x * at1.x; q.y = yv.y * at1.y;
            q.z = yv.z * at1.z; q.w = yv.w * at1.w;
            __stcs(ob + (size_t)ch * HW4 + p1, q);
        }
    }
}

extern "C" void kernel_launch(void* const* d_in, const int* in_sizes, int n_in,
                              void* d_out, int out_size) {
    const float* x  = (const float*)d_in[0];
    const float* w1 = (const float*)d_in[1];
    const float* g1 = (const float*)d_in[2];
    const float* b1 = (const float*)d_in[3];
    const float* m1 = (const float*)d_in[4];
    const float* v1 = (const float*)d_in[5];
    const float* w2 = (const float*)d_in[6];
    const float* g2 = (const float*)d_in[7];
    const float* b2 = (const float*)d_in[8];
    const float* m2 = (const float*)d_in[9];
    const float* v2 = (const float*)d_in[10];
    const float* w3 = (const float*)d_in[11];
    const float* g3 = (const float*)d_in[12];
    const float* b3 = (const float*)d_in[13];
    const float* m3 = (const float*)d_in[14];
    const float* v3 = (const float*)d_in[15];
    float* out = (float*)d_out;

    static bool attr_set = false;
    if (!attr_set) {
        cudaFuncSetAttribute(fused_kernel,
                             cudaFuncAttributeMaxDynamicSharedMemorySize, SMEM_BYTES);
        attr_set = true;
    }

    fused_kernel<<<BATCH * CLUS, THREADS, SMEM_BYTES>>>(
        x, out,
        w1, g1, b1, m1, v1,
        w2, g2, b2, m2, v2,
        w3, g3, b3, m3, v3);
}

// round 7
// speedup vs baseline: 2.5700x; 2.5700x over previous
#include <cuda_runtime.h>
#include <cuda_bf16.h>

// Problem constants
#define BATCH 32
#define CH    256
#define HH    64
#define WW    64
#define HW    (HH*WW)            // 4096
#define HW4   (HW/4)             // 1024 float4 per image plane
#define EPSV  1e-5f

#define CHUNKS   8               // channel chunks per block (pool)
#define CPC      (CH/CHUNKS)     // 32 channels per chunk
#define PIX      32              // float4 pixels per block (pool)

// Scratch (allocation-free rule: __device__ globals)
__device__ float g_pooled[BATCH * 2 * HW];   // [B, {max,mean}, H, W]
__device__ float g_att[BATCH * HW];          // [B, H, W]

// ---------------------------------------------------------------------------
// Kernel 1: channel pooling (max + mean over C) -> g_pooled  (R1-proven)
// Block = 256 threads = 32 float4-pixels x 8 channel-chunks, grid = 1024.
// ---------------------------------------------------------------------------
__global__ __launch_bounds__(256) void pool_kernel(const float* __restrict__ x) {
    __shared__ float4 smx[CHUNKS * PIX];
    __shared__ float4 ssm[CHUNKS * PIX];

    int tid   = threadIdx.x;
    int pix   = tid & (PIX - 1);       // 0..31
    int chunk = tid >> 5;              // 0..7

    int blk    = blockIdx.x;           // 0..1023
    int b      = blk >> 5;             // 32 blocks per batch
    int p4base = (blk & 31) * PIX;
    int p4     = p4base + pix;

    const float4* xb = (const float4*)(x + (size_t)b * CH * HW) + p4
                     + (size_t)(chunk * CPC) * HW4;

    float4 v  = xb[0];
    float4 mx = v;
    float4 sm = v;
#pragma unroll
    for (int c = 1; c < CPC; c++) {
        float4 t = xb[(size_t)c * HW4];
        mx.x = fmaxf(mx.x, t.x); mx.y = fmaxf(mx.y, t.y);
        mx.z = fmaxf(mx.z, t.z); mx.w = fmaxf(mx.w, t.w);
        sm.x += t.x; sm.y += t.y; sm.z += t.z; sm.w += t.w;
    }
    smx[tid] = mx;
    ssm[tid] = sm;
    __syncthreads();

#pragma unroll
    for (int s = 128; s >= PIX; s >>= 1) {
        if (tid < s) {
            float4 am = smx[tid], bm = smx[tid + s];
            am.x = fmaxf(am.x, bm.x); am.y = fmaxf(am.y, bm.y);
            am.z = fmaxf(am.z, bm.z); am.w = fmaxf(am.w, bm.w);
            smx[tid] = am;
            float4 as = ssm[tid], bs = ssm[tid + s];
            as.x += bs.x; as.y += bs.y; as.z += bs.z; as.w += bs.w;
            ssm[tid] = as;
        }
        __syncthreads();
    }

    if (tid < PIX) {
        const float inv = 1.0f / (float)CH;
        float4 mxr = smx[tid];
        float4 smr = ssm[tid];
        float4 av = make_float4(smr.x * inv, smr.y * inv, smr.z * inv, smr.w * inv);
        float4* pmax = (float4*)(g_pooled + (size_t)b * 2 * HW) + p4base + tid;
        float4* pavg = (float4*)(g_pooled + (size_t)b * 2 * HW + HW) + p4base + tid;
        *pmax = mxr;
        *pavg = av;
    }
}

// ---------------------------------------------------------------------------
// Kernel 2: 3x (7x7 conv 2->1 + BN + sigmoid), averaged -> g_att  (R1-proven)
// ---------------------------------------------------------------------------
__global__ void att_kernel(const float* __restrict__ w1,
                           const float* __restrict__ g1, const float* __restrict__ b1,
                           const float* __restrict__ m1, const float* __restrict__ v1,
                           const float* __restrict__ w2,
                           const float* __restrict__ g2, const float* __restrict__ b2,
                           const float* __restrict__ m2, const float* __restrict__ v2,
                           const float* __restrict__ w3,
                           const float* __restrict__ g3, const float* __restrict__ b3,
                           const float* __restrict__ m3, const float* __restrict__ v3) {
    __shared__ float ws[3][2][49];   // BN-scaled effective weights
    __shared__ float bias[3];

    int tid = threadIdx.x;

    if (tid < 3) {
        const float* g  = (tid == 0) ? g1 : (tid == 1) ? g2 : g3;
        const float* be = (tid == 0) ? b1 : (tid == 1) ? b2 : b3;
        const float* m  = (tid == 0) ? m1 : (tid == 1) ? m2 : m3;
        const float* v  = (tid == 0) ? v1 : (tid == 1) ? v2 : v3;
        float s = g[0] * rsqrtf(v[0] + EPSV);
        bias[tid] = be[0] - m[0] * s;
    }

    for (int k = tid; k < 3 * 2 * 49; k += blockDim.x) {
        int br = k / 98;
        int r  = k % 98;
        int i  = r / 49;
        int kk = r % 49;
        int kh = kk / 7, kw = kk % 7;
        float s, raw;
        if (br == 0) {
            s = g1[0] * rsqrtf(v1[0] + EPSV);
            raw = w1[i * 49 + kh * 7 + kw];
        } else if (br == 1) {
            s = g2[0] * rsqrtf(v2[0] + EPSV);
            raw = w2[i * 49 + kw * 7 + kh];   // transposed kernel
        } else {
            s = g3[0] * rsqrtf(v3[0] + EPSV);
            raw = w3[i * 49 + kh * 7 + kw];
        }
        ws[br][i][kk] = raw * s;
    }
    __syncthreads();

    int blk = blockIdx.x;
    int b = blk >> 4;                 // / 16
    int row_base = (blk & 15) * 4;
    int h = row_base + (tid >> 6);
    int w = tid & 63;

    const float* pmax = g_pooled + (size_t)b * 2 * HW;
    const float* pavg = pmax + HW;

    float acc0 = 0.f, acc1 = 0.f, acc2 = 0.f;
#pragma unroll
    for (int kh = 0; kh < 7; kh++) {
        int hh = h + kh - 3;
        if (hh < 0 || hh >= HH) continue;
#pragma unroll
        for (int kw = 0; kw < 7; kw++) {
            int wv = w + kw - 3;
            if (wv < 0 || wv >= WW) continue;
            int off = hh * WW + wv;
            float pm = pmax[off];
            float pa = pavg[off];
            int kk = kh * 7 + kw;
            acc0 = fmaf(ws[0][0][kk], pm, acc0);
            acc0 = fmaf(ws[0][1][kk], pa, acc0);
            acc1 = fmaf(ws[1][0][kk], pm, acc1);
            acc1 = fmaf(ws[1][1][kk], pa, acc1);
            acc2 = fmaf(ws[2][0][kk], pm, acc2);
            acc2 = fmaf(ws[2][1][kk], pa, acc2);
        }
    }
    float s0 = 1.0f / (1.0f + __expf(-(acc0 + bias[0])));
    float s1 = 1.0f / (1.0f + __expf(-(acc1 + bias[1])));
    float s2 = 1.0f / (1.0f + __expf(-(acc2 + bias[2])));
    g_att[(size_t)b * HW + h * WW + w] = (s0 + s1 + s2) * (1.0f / 3.0f);
}

// ---------------------------------------------------------------------------
// Kernel 3: out = x * att, ILP=4.
// One block per (image, channel) plane (8192 blocks); each thread handles
// 4 float4 with front-batched independent loads (8 LDG.128 in flight).
// att plane (4KB) is L2-hot.
// ---------------------------------------------------------------------------
__global__ __launch_bounds__(256) void mul_kernel(const float* __restrict__ x,
                                                  float* __restrict__ out) {
    int blk = blockIdx.x;              // b*CH + c
    int tid = threadIdx.x;
    int b   = blk >> 8;

    const float4* xp = (const float4*)x + (size_t)blk * HW4;
    float4*       op = (float4*)out    + (size_t)blk * HW4;
    const float4* ap = (const float4*)g_att + (size_t)b * HW4;

    float4 xv[4], av[4];
#pragma unroll
    for (int i = 0; i < 4; i++) xv[i] = xp[tid + i * 256];
#pragma unroll
    for (int i = 0; i < 4; i++) av[i] = ap[tid + i * 256];
#pragma unroll
    for (int i = 0; i < 4; i++) {
        float4 o;
        o.x = xv[i].x * av[i].x; o.y = xv[i].y * av[i].y;
        o.z = xv[i].z * av[i].z; o.w = xv[i].w * av[i].w;
        op[tid + i * 256] = o;
    }
}

extern "C" void kernel_launch(void* const* d_in, const int* in_sizes, int n_in,
                              void* d_out, int out_size) {
    const float* x  = (const float*)d_in[0];
    const float* w1 = (const float*)d_in[1];
    const float* g1 = (const float*)d_in[2];
    const float* b1 = (const float*)d_in[3];
    const float* m1 = (const float*)d_in[4];
    const float* v1 = (const float*)d_in[5];
    const float* w2 = (const float*)d_in[6];
    const float* g2 = (const float*)d_in[7];
    const float* b2 = (const float*)d_in[8];
    const float* m2 = (const float*)d_in[9];
    const float* v2 = (const float*)d_in[10];
    const float* w3 = (const float*)d_in[11];
    const float* g3 = (const float*)d_in[12];
    const float* b3 = (const float*)d_in[13];
    const float* m3 = (const float*)d_in[14];
    const float* v3 = (const float*)d_in[15];
    float* out = (float*)d_out;

    // K1: pooling  (1024 blocks, R1-proven)
    pool_kernel<<<BATCH * HW4 / PIX, 256>>>(x);

    // K2: attention map
    att_kernel<<<BATCH * (HH / 4), 256>>>(w1, g1, b1, m1, v1,
                                          w2, g2, b2, m2, v2,
                                          w3, g3, b3, m3, v3);

    // K3: elementwise multiply, one block per (b, c) plane
    mul_kernel<<<BATCH * CH, 256>>>(x, out);
}

// round 11
// speedup vs baseline: 2.5934x; 1.0091x over previous
#include <cuda_runtime.h>
#include <cuda_bf16.h>

// Problem constants
#define BATCH 32
#define CH    256
#define HH    64
#define WW    64
#define HW    (HH*WW)            // 4096
#define HW4   (HW/4)             // 1024 float4 per image plane
#define EPSV  1e-5f

#define CHUNKS   8               // channel chunks per block (pool)
#define CPC      (CH/CHUNKS)     // 32 channels per chunk
#define PIX      32              // float4 pixels per block (pool)

// Scratch (allocation-free rule: __device__ globals)
__device__ float g_pooled[BATCH * 2 * HW];   // [B, {max,mean}, H, W]
__device__ float g_att[BATCH * HW];          // [B, H, W]

// ---------------------------------------------------------------------------
// Kernel 1: channel pooling (max + mean over C) -> g_pooled  (R1-proven)
// Block = 256 threads = 32 float4-pixels x 8 channel-chunks, grid = 1024.
// Default load policy caches x in L2; mul re-reads the tail in reverse.
// ---------------------------------------------------------------------------
__global__ __launch_bounds__(256) void pool_kernel(const float* __restrict__ x) {
    __shared__ float4 smx[CHUNKS * PIX];
    __shared__ float4 ssm[CHUNKS * PIX];

    int tid   = threadIdx.x;
    int pix   = tid & (PIX - 1);       // 0..31
    int chunk = tid >> 5;              // 0..7

    int blk    = blockIdx.x;           // 0..1023
    int b      = blk >> 5;             // 32 blocks per batch
    int p4base = (blk & 31) * PIX;
    int p4     = p4base + pix;

    const float4* xb = (const float4*)(x + (size_t)b * CH * HW) + p4
                     + (size_t)(chunk * CPC) * HW4;

    float4 v  = xb[0];
    float4 mx = v;
    float4 sm = v;
#pragma unroll
    for (int c = 1; c < CPC; c++) {
        float4 t = xb[(size_t)c * HW4];
        mx.x = fmaxf(mx.x, t.x); mx.y = fmaxf(mx.y, t.y);
        mx.z = fmaxf(mx.z, t.z); mx.w = fmaxf(mx.w, t.w);
        sm.x += t.x; sm.y += t.y; sm.z += t.z; sm.w += t.w;
    }
    smx[tid] = mx;
    ssm[tid] = sm;
    __syncthreads();

#pragma unroll
    for (int s = 128; s >= PIX; s >>= 1) {
        if (tid < s) {
            float4 am = smx[tid], bm = smx[tid + s];
            am.x = fmaxf(am.x, bm.x); am.y = fmaxf(am.y, bm.y);
            am.z = fmaxf(am.z, bm.z); am.w = fmaxf(am.w, bm.w);
            smx[tid] = am;
            float4 as = ssm[tid], bs = ssm[tid + s];
            as.x += bs.x; as.y += bs.y; as.z += bs.z; as.w += bs.w;
            ssm[tid] = as;
        }
        __syncthreads();
    }

    if (tid < PIX) {
        const float inv = 1.0f / (float)CH;
        float4 mxr = smx[tid];
        float4 smr = ssm[tid];
        float4 av = make_float4(smr.x * inv, smr.y * inv, smr.z * inv, smr.w * inv);
        float4* pmax = (float4*)(g_pooled + (size_t)b * 2 * HW) + p4base + tid;
        float4* pavg = (float4*)(g_pooled + (size_t)b * 2 * HW + HW) + p4base + tid;
        *pmax = mxr;
        *pavg = av;
    }
}

// ---------------------------------------------------------------------------
// Kernel 2: 3x (7x7 conv 2->1 + BN + sigmoid), averaged -> g_att  (R1-proven)
// ---------------------------------------------------------------------------
__global__ void att_kernel(const float* __restrict__ w1,
                           const float* __restrict__ g1, const float* __restrict__ b1,
                           const float* __restrict__ m1, const float* __restrict__ v1,
                           const float* __restrict__ w2,
                           const float* __restrict__ g2, const float* __restrict__ b2,
                           const float* __restrict__ m2, const float* __restrict__ v2,
                           const float* __restrict__ w3,
                           const float* __restrict__ g3, const float* __restrict__ b3,
                           const float* __restrict__ m3, const float* __restrict__ v3) {
    __shared__ float ws[3][2][49];   // BN-scaled effective weights
    __shared__ float bias[3];

    int tid = threadIdx.x;

    if (tid < 3) {
        const float* g  = (tid == 0) ? g1 : (tid == 1) ? g2 : g3;
        const float* be = (tid == 0) ? b1 : (tid == 1) ? b2 : b3;
        const float* m  = (tid == 0) ? m1 : (tid == 1) ? m2 : m3;
        const float* v  = (tid == 0) ? v1 : (tid == 1) ? v2 : v3;
        float s = g[0] * rsqrtf(v[0] + EPSV);
        bias[tid] = be[0] - m[0] * s;
    }

    for (int k = tid; k < 3 * 2 * 49; k += blockDim.x) {
        int br = k / 98;
        int r  = k % 98;
        int i  = r / 49;
        int kk = r % 49;
        int kh = kk / 7, kw = kk % 7;
        float s, raw;
        if (br == 0) {
            s = g1[0] * rsqrtf(v1[0] + EPSV);
            raw = w1[i * 49 + kh * 7 + kw];
        } else if (br == 1) {
            s = g2[0] * rsqrtf(v2[0] + EPSV);
            raw = w2[i * 49 + kw * 7 + kh];   // transposed kernel
        } else {
            s = g3[0] * rsqrtf(v3[0] + EPSV);
            raw = w3[i * 49 + kh * 7 + kw];
        }
        ws[br][i][kk] = raw * s;
    }
    __syncthreads();

    int blk = blockIdx.x;
    int b = blk >> 4;                 // / 16
    int row_base = (blk & 15) * 4;
    int h = row_base + (tid >> 6);
    int w = tid & 63;

    const float* pmax = g_pooled + (size_t)b * 2 * HW;
    const float* pavg = pmax + HW;

    float acc0 = 0.f, acc1 = 0.f, acc2 = 0.f;
#pragma unroll
    for (int kh = 0; kh < 7; kh++) {
        int hh = h + kh - 3;
        if (hh < 0 || hh >= HH) continue;
#pragma unroll
        for (int kw = 0; kw < 7; kw++) {
            int wv = w + kw - 3;
            if (wv < 0 || wv >= WW) continue;
            int off = hh * WW + wv;
            float pm = pmax[off];
            float pa = pavg[off];
            int kk = kh * 7 + kw;
            acc0 = fmaf(ws[0][0][kk], pm, acc0);
            acc0 = fmaf(ws[0][1][kk], pa, acc0);
            acc1 = fmaf(ws[1][0][kk], pm, acc1);
            acc1 = fmaf(ws[1][1][kk], pa, acc1);
            acc2 = fmaf(ws[2][0][kk], pm, acc2);
            acc2 = fmaf(ws[2][1][kk], pa, acc2);
        }
    }
    float s0 = 1.0f / (1.0f + __expf(-(acc0 + bias[0])));
    float s1 = 1.0f / (1.0f + __expf(-(acc1 + bias[1])));
    float s2 = 1.0f / (1.0f + __expf(-(acc2 + bias[2])));
    g_att[(size_t)b * HW + h * WW + w] = (s0 + s1 + s2) * (1.0f / 3.0f);
}

// ---------------------------------------------------------------------------
// Kernel 3: out = x * att, ILP=4, REVERSED plane order.
// Pool streamed x ascending, so L2 holds the tail of x; consuming planes in
// descending order turns that tail into L2 hits. __stcs stores keep the
// output from displacing x via write-allocation.
// ---------------------------------------------------------------------------
__global__ __launch_bounds__(256) void mul_kernel(const float* __restrict__ x,
                                                  float* __restrict__ out) {
    int blk = (BATCH * CH - 1) - blockIdx.x;   // reversed plane index: b*CH + c
    int tid = threadIdx.x;
    int b   = blk >> 8;

    const float4* xp = (const float4*)x + (size_t)blk * HW4;
    float4*       op = (float4*)out    + (size_t)blk * HW4;
    const float4* ap = (const float4*)g_att + (size_t)b * HW4;

    float4 xv[4], av[4];
#pragma unroll
    for (int i = 0; i < 4; i++) xv[i] = xp[tid + i * 256];
#pragma unroll
    for (int i = 0; i < 4; i++) av[i] = ap[tid + i * 256];
#pragma unroll
    for (int i = 0; i < 4; i++) {
        float4 o;
        o.x = xv[i].x * av[i].x; o.y = xv[i].y * av[i].y;
        o.z = xv[i].z * av[i].z; o.w = xv[i].w * av[i].w;
        __stcs(op + tid + i * 256, o);
    }
}

extern "C" void kernel_launch(void* const* d_in, const int* in_sizes, int n_in,
                              void* d_out, int out_size) {
    const float* x  = (const float*)d_in[0];
    const float* w1 = (const float*)d_in[1];
    const float* g1 = (const float*)d_in[2];
    const float* b1 = (const float*)d_in[3];
    const float* m1 = (const float*)d_in[4];
    const float* v1 = (const float*)d_in[5];
    const float* w2 = (const float*)d_in[6];
    const float* g2 = (const float*)d_in[7];
    const float* b2 = (const float*)d_in[8];
    const float* m2 = (const float*)d_in[9];
    const float* v2 = (const float*)d_in[10];
    const float* w3 = (const float*)d_in[11];
    const float* g3 = (const float*)d_in[12];
    const float* b3 = (const float*)d_in[13];
    const float* m3 = (const float*)d_in[14];
    const float* v3 = (const float*)d_in[15];
    float* out = (float*)d_out;

    // K1: pooling  (1024 blocks, R1-proven)
    pool_kernel<<<BATCH * HW4 / PIX, 256>>>(x);

    // K2: attention map
    att_kernel<<<BATCH * (HH / 4), 256>>>(w1, g1, b1, m1, v1,
                                          w2, g2, b2, m2, v2,
                                          w3, g3, b3, m3, v3);

    // K3: elementwise multiply, one block per (b, c) plane, reversed order
    mul_kernel<<<BATCH * CH, 256>>>(x, out);
}